// round 7
// baseline (speedup 1.0000x reference)
#include <cuda_runtime.h>
#include <cuda_fp16.h>
#include <cstdint>

#define SMEM_TOTAL 135168

// ---- tcgen05-path smem offsets ----
#define OFF_TMEM 0
#define OFF_MBAR 8
#define OFF_Z    2112
#define Z_STRIDE 528
#define OFF_A    36864
#define OFF_B    69632
#define IDESC ((1u<<4) | (32u<<17) | (8u<<24))   // f32 accum, f16 in, N=256, M=128

__device__ uint32_t g_wtile[4][8192];   // tcgen05 A: per K-chunk [256o][64c] fp16 SW128
__device__ uint32_t g_wfrag[32768];     // mma.sync A fragments: [wb(8)][lane(32)][fi(128)]

__device__ __forceinline__ uint32_t s2u(const void* p){
    uint32_t a;
    asm("{ .reg .u64 t; cvta.to.shared.u64 t, %1; cvt.u32.u64 %0, t; }" : "=r"(a) : "l"(p));
    return a;
}

// ---------------- weight prep (both layouts) ----------------
__global__ void __launch_bounds__(256) prep_weights(const float* __restrict__ cw){
    const int idx = blockIdx.x * 256 + threadIdx.x;      // 32768
    {   // tcgen05 layout
        int o = idx >> 7;
        int c = (idx & 127) * 2;
        float2 wv = *(const float2*)(cw + o * 256 + c);
        __half2 hw = __floats2half2_rn(wv.x, wv.y);
        int chunk = c >> 6, cc = c & 63;
        uint32_t off = (uint32_t)(o * 128 + cc * 2) ^ (uint32_t)((o & 7) << 4);
        *(uint32_t*)((char*)g_wtile[chunk] + off) = *(uint32_t*)&hw;
    }
    {   // mma.sync fragment layout
        int wb = idx >> 12;
        int ln = (idx >> 7) & 31;
        int fi = idx & 127;
        int kt = fi >> 3, mt = (fi >> 2) & 1, j = fi & 3;
        int o = wb * 32 + mt * 16 + (ln >> 2) + (j & 1) * 8;
        int c = kt * 16 + (ln & 3) * 2 + (j >> 1) * 8;
        float2 wv = *(const float2*)(cw + o * 256 + c);
        __half2 hw = __floats2half2_rn(wv.x, wv.y);
        g_wfrag[idx] = *(uint32_t*)&hw;
    }
}

#if defined(__CUDA_ARCH__) && defined(__CUDA_ARCH_FEAT_SM103_ALL)
__device__ __forceinline__ uint32_t elect1(){
    uint32_t p;
    asm volatile("{ .reg .pred p; elect.sync _|p, 0xFFFFFFFF; selp.b32 %0, 1, 0, p; }" : "=r"(p));
    return p;
}
__device__ __forceinline__ uint64_t mkdesc(uint32_t a){
    const uint64_t base = (2ull<<61) | (1ull<<46) | (64ull<<32) | (1ull<<16);
    return base | (uint64_t)((a >> 4) & 0x3FFFu);
}
__device__ __forceinline__ void mma_f16(uint32_t d, uint64_t ad, uint64_t bd, uint32_t en){
    asm volatile(
        "{\n\t.reg .pred p;\n\tsetp.ne.u32 p, %5, 0;\n\t"
        "tcgen05.mma.cta_group::1.kind::f16 [%0], %1, %2, %3, {%4,%4,%4,%4}, p;\n\t}"
        :: "r"(d), "l"(ad), "l"(bd), "r"(IDESC), "r"(0u), "r"(en) : "memory");
}
__device__ __forceinline__ void mbar_wait(uint32_t mbar, uint32_t parity){
    asm volatile(
        "{\n\t.reg .pred P;\n"
        "LW%=:\n\tmbarrier.try_wait.parity.acquire.cta.shared::cta.b64 P, [%0], %1, 0x989680;\n"
        "\t@P bra LD%=;\n\tbra LW%=;\n"
        "LD%=:\n\t}" :: "r"(mbar), "r"(parity) : "memory");
}
#endif

// ---------------- fused kernel ----------------
__global__ void __launch_bounds__(256, 1)
fused_ln_conv_relu(const float* __restrict__ x, const float* __restrict__ y,
                   const float* __restrict__ lnw, const float* __restrict__ lnb,
                   float* __restrict__ out)
{
    extern __shared__ __align__(1024) char smem[];
    const uint32_t su = s2u(smem);
    const int tid = threadIdx.x, wid = tid >> 5, lane = tid & 31;
    const int b = blockIdx.x >> 8, h = blockIdx.x & 255;
    const size_t base_bh = ((size_t)b << 24) + ((size_t)h << 8);

    const float4 lwa = *(const float4*)(lnw + 4 * lane);
    const float4 lwb = *(const float4*)(lnw + 128 + 4 * lane);
    const float4 lba = *(const float4*)(lnb + 4 * lane);
    const float4 lbb = *(const float4*)(lnb + 128 + 4 * lane);

#if defined(__CUDA_ARCH__) && defined(__CUDA_ARCH_FEAT_SM103_ALL)
    // ================= tcgen05 path =================
    if (wid == 0) {
        if (lane == 0)
            asm volatile("mbarrier.init.shared.b64 [%0], 1;" :: "r"(su + OFF_MBAR) : "memory");
        __syncwarp();
        asm volatile("tcgen05.alloc.cta_group::1.sync.aligned.shared::cta.b32 [%0], %1;"
                     :: "r"(su + OFF_TMEM), "r"(512u) : "memory");
        asm volatile("tcgen05.relinquish_alloc_permit.cta_group::1.sync.aligned;");
    }
    __syncthreads();
    uint32_t tmem;
    asm volatile("ld.shared.b32 %0, [%1];" : "=r"(tmem) : "r"(su + OFF_TMEM));

    #pragma unroll 1
    for (int kc = 0; kc < 4; kc++) {
        if (kc) mbar_wait(su + OFF_MBAR, (kc - 1) & 1);

        {   // A chunk copy (pre-swizzled fp16 weights)
            const uint4* wsrc = (const uint4*)g_wtile[kc];
            uint4* adst = (uint4*)(smem + OFF_A);
            #pragma unroll
            for (int i = 0; i < 8; i++) adst[tid + 256 * i] = wsrc[tid + 256 * i];
        }
        {   // LN -> Z (fp16 [64c][256w])
            const float* px = x + base_bh + ((size_t)(kc * 64 + wid * 8) << 16) + 4 * lane;
            const float* py = y + base_bh + ((size_t)(kc * 64 + wid * 8) << 16) + 4 * lane;
            #pragma unroll
            for (int i = 0; i < 8; i++) {
                float4 xa = *(const float4*)px;
                float4 xb = *(const float4*)(px + 128);
                float4 ya = *(const float4*)py;
                float4 yb = *(const float4*)(py + 128);
                px += 65536; py += 65536;
                float v0 = xa.x + ya.x, v1 = xa.y + ya.y, v2 = xa.z + ya.z, v3 = xa.w + ya.w;
                float v4 = xb.x + yb.x, v5 = xb.y + yb.y, v6 = xb.z + yb.z, v7 = xb.w + yb.w;
                float s = v0+v1+v2+v3+v4+v5+v6+v7;
                float q = v0*v0+v1*v1+v2*v2+v3*v3+v4*v4+v5*v5+v6*v6+v7*v7;
                #pragma unroll
                for (int o_ = 16; o_; o_ >>= 1) {
                    s += __shfl_xor_sync(0xFFFFFFFFu, s, o_);
                    q += __shfl_xor_sync(0xFFFFFFFFu, q, o_);
                }
                const float mean = s * (1.0f / 256.0f);
                const float rstd = rsqrtf(q * (1.0f / 256.0f) - mean * mean + 1e-5f);
                __half2 h01 = __floats2half2_rn((v0-mean)*rstd*lwa.x + lba.x, (v1-mean)*rstd*lwa.y + lba.y);
                __half2 h23 = __floats2half2_rn((v2-mean)*rstd*lwa.z + lba.z, (v3-mean)*rstd*lwa.w + lba.w);
                __half2 h45 = __floats2half2_rn((v4-mean)*rstd*lwb.x + lbb.x, (v5-mean)*rstd*lwb.y + lbb.y);
                __half2 h67 = __floats2half2_rn((v6-mean)*rstd*lwb.z + lbb.z, (v7-mean)*rstd*lwb.w + lbb.w);
                char* zr = smem + OFF_Z + (wid * 8 + i) * Z_STRIDE;
                *(uint2*)(zr + 8 * lane)       = make_uint2(*(uint32_t*)&h01, *(uint32_t*)&h23);
                *(uint2*)(zr + 256 + 8 * lane) = make_uint2(*(uint32_t*)&h45, *(uint32_t*)&h67);
            }
        }
        __syncthreads();

        {   // transpose Z [64c][256w] -> B [256w][64c] K-major SW128
            const int g = lane >> 3, r = lane & 7;
            #pragma unroll
            for (int j = 0; j < 8; j++) {
                const int t = wid * 8 + j;
                const int ct = t >> 4, wt = t & 15;
                const int c_src = ct * 16 + (g & 1) * 8 + r;
                const int w_src = wt * 16 + (g >> 1) * 8;
                uint32_t r0, r1, r2, r3;
                asm volatile("ldmatrix.sync.aligned.m8n8.x4.shared.b16 {%0,%1,%2,%3}, [%4];"
                             : "=r"(r0), "=r"(r1), "=r"(r2), "=r"(r3)
                             : "r"(su + OFF_Z + (uint32_t)(c_src * Z_STRIDE + w_src * 2)));
                const int w_d = wt * 16 + (g >> 1) * 8 + r;
                const int c_d = ct * 16 + (g & 1) * 8;
                uint32_t off = (uint32_t)(w_d * 128 + c_d * 2);
                off ^= ((off >> 3) & 0x70);
                asm volatile("stmatrix.sync.aligned.m8n8.x4.trans.shared.b16 [%0], {%1,%2,%3,%4};"
                             :: "r"(su + OFF_B + off), "r"(r0), "r"(r1), "r"(r2), "r"(r3));
            }
        }
        asm volatile("fence.proxy.async.shared::cta;" ::: "memory");
        __syncthreads();

        if (wid == 0) {
            asm volatile("tcgen05.fence::after_thread_sync;" ::: "memory");
            const uint64_t ad = mkdesc(su + OFF_A);
            const uint64_t bd = mkdesc(su + OFF_B);
            if (elect1()) {
                #pragma unroll
                for (int s = 0; s < 4; s++)
                    mma_f16(tmem,        ad + 2*s,        bd + 2*s, (kc | s) ? 1u : 0u);
                #pragma unroll
                for (int s = 0; s < 4; s++)
                    mma_f16(tmem + 256,  ad + 1024 + 2*s, bd + 2*s, (kc | s) ? 1u : 0u);
                asm volatile(
                    "tcgen05.commit.cta_group::1.mbarrier::arrive::one.shared::cluster.b64 [%0];"
                    :: "r"(su + OFF_MBAR) : "memory");
            }
        }
    }

    mbar_wait(su + OFF_MBAR, 1);
    asm volatile("tcgen05.fence::after_thread_sync;" ::: "memory");

    {   // epilogue: TMEM -> ReLU -> smem transpose -> coalesced stores
        const int o_base = (wid & 3) * 32 + (wid >> 2) * 128;
        const uint32_t colbase = (uint32_t)(wid >> 2) * 256;
        float* tile = (float*)(smem + OFF_Z + wid * 4224);
        float* outp = out + ((size_t)b << 24) + ((size_t)o_base << 16) + ((size_t)h << 8);
        #pragma unroll 1
        for (int gblk = 0; gblk < 8; gblk++) {
            uint32_t r[32];
            asm volatile(
                "tcgen05.ld.sync.aligned.32x32b.x32.b32 "
                "{%0,%1,%2,%3,%4,%5,%6,%7,%8,%9,%10,%11,%12,%13,%14,%15,"
                "%16,%17,%18,%19,%20,%21,%22,%23,%24,%25,%26,%27,%28,%29,%30,%31}, [%32];"
                : "=r"(r[0]),"=r"(r[1]),"=r"(r[2]),"=r"(r[3]),"=r"(r[4]),"=r"(r[5]),"=r"(r[6]),"=r"(r[7]),
                  "=r"(r[8]),"=r"(r[9]),"=r"(r[10]),"=r"(r[11]),"=r"(r[12]),"=r"(r[13]),"=r"(r[14]),"=r"(r[15]),
                  "=r"(r[16]),"=r"(r[17]),"=r"(r[18]),"=r"(r[19]),"=r"(r[20]),"=r"(r[21]),"=r"(r[22]),"=r"(r[23]),
                  "=r"(r[24]),"=r"(r[25]),"=r"(r[26]),"=r"(r[27]),"=r"(r[28]),"=r"(r[29]),"=r"(r[30]),"=r"(r[31])
                : "r"(tmem + colbase + (uint32_t)gblk * 32));
            asm volatile("tcgen05.wait::ld.sync.aligned;" ::: "memory");
            #pragma unroll
            for (int i = 0; i < 32; i++)
                tile[lane * 33 + i] = fmaxf(__uint_as_float(r[i]), 0.0f);
            __syncwarp();
            #pragma unroll
            for (int o2 = 0; o2 < 32; o2++)
                outp[(size_t)o2 * 65536 + gblk * 32 + lane] = tile[o2 * 33 + lane];
            __syncwarp();
        }
    }

    __syncthreads();
    if (wid == 0) {
        if (lane == 0)
            asm volatile("mbarrier.inval.shared.b64 [%0];" :: "r"(su + OFF_MBAR) : "memory");
        asm volatile("tcgen05.dealloc.cta_group::1.sync.aligned.b32 %0, %1;" :: "r"(tmem), "r"(512u));
    }
#else
    // ================= mma.sync fallback (sm_103 base) =================
    // Z: full [256c][256w] fp16, row stride 528B, at smem offset 0 (132 KB)
    {
        #pragma unroll 4
        for (int r = 0; r < 32; r++) {
            const int c = wid * 32 + r;
            const float* px = x + base_bh + ((size_t)c << 16) + 4 * lane;
            const float* py = y + base_bh + ((size_t)c << 16) + 4 * lane;
            float4 xa = *(const float4*)px;
            float4 xb = *(const float4*)(px + 128);
            float4 ya = *(const float4*)py;
            float4 yb = *(const float4*)(py + 128);
            float v0 = xa.x + ya.x, v1 = xa.y + ya.y, v2 = xa.z + ya.z, v3 = xa.w + ya.w;
            float v4 = xb.x + yb.x, v5 = xb.y + yb.y, v6 = xb.z + yb.z, v7 = xb.w + yb.w;
            float s = v0+v1+v2+v3+v4+v5+v6+v7;
            float q = v0*v0+v1*v1+v2*v2+v3*v3+v4*v4+v5*v5+v6*v6+v7*v7;
            #pragma unroll
            for (int o_ = 16; o_; o_ >>= 1) {
                s += __shfl_xor_sync(0xFFFFFFFFu, s, o_);
                q += __shfl_xor_sync(0xFFFFFFFFu, q, o_);
            }
            const float mean = s * (1.0f / 256.0f);
            const float rstd = rsqrtf(q * (1.0f / 256.0f) - mean * mean + 1e-5f);
            __half2 h01 = __floats2half2_rn((v0-mean)*rstd*lwa.x + lba.x, (v1-mean)*rstd*lwa.y + lba.y);
            __half2 h23 = __floats2half2_rn((v2-mean)*rstd*lwa.z + lba.z, (v3-mean)*rstd*lwa.w + lba.w);
            __half2 h45 = __floats2half2_rn((v4-mean)*rstd*lwb.x + lbb.x, (v5-mean)*rstd*lwb.y + lbb.y);
            __half2 h67 = __floats2half2_rn((v6-mean)*rstd*lwb.z + lbb.z, (v7-mean)*rstd*lwb.w + lbb.w);
            char* zr = smem + c * 528;
            *(uint2*)(zr + 8 * lane)       = make_uint2(*(uint32_t*)&h01, *(uint32_t*)&h23);
            *(uint2*)(zr + 256 + 8 * lane) = make_uint2(*(uint32_t*)&h45, *(uint32_t*)&h67);
        }
    }
    __syncthreads();

    // warp wid owns o-block [wid*32, wid*32+32); loop w in 4 chunks of 64
    const uint4* wf = (const uint4*)g_wfrag + (wid * 32 + lane) * 32;
    const int g = lane >> 2, t = lane & 3;
    const uint32_t krow_off = ((uint32_t)((lane >> 3) & 1)) * 8 + (lane & 7);
    const uint32_t ncol_off = ((uint32_t)(lane >> 4)) * 8;

    #pragma unroll 1
    for (int wc = 0; wc < 4; wc++) {
        float acc[2][8][4] = {};
        #pragma unroll 2
        for (int kt = 0; kt < 16; kt++) {
            uint32_t bf[8][2];
            #pragma unroll
            for (int qq = 0; qq < 4; qq++) {
                uint32_t addr = su + (kt * 16 + krow_off) * 528
                                   + (uint32_t)(wc * 64 + qq * 16) * 2 + ncol_off * 2;
                asm volatile("ldmatrix.sync.aligned.m8n8.x4.trans.shared.b16 {%0,%1,%2,%3}, [%4];"
                             : "=r"(bf[2*qq][0]), "=r"(bf[2*qq][1]),
                               "=r"(bf[2*qq+1][0]), "=r"(bf[2*qq+1][1])
                             : "r"(addr));
            }
            uint4 a0 = __ldg(wf + kt * 2);
            uint4 a1 = __ldg(wf + kt * 2 + 1);
            #pragma unroll
            for (int nt = 0; nt < 8; nt++) {
                asm volatile(
                    "mma.sync.aligned.m16n8k16.row.col.f32.f16.f16.f32 "
                    "{%0,%1,%2,%3}, {%4,%5,%6,%7}, {%8,%9}, {%0,%1,%2,%3};"
                    : "+f"(acc[0][nt][0]), "+f"(acc[0][nt][1]), "+f"(acc[0][nt][2]), "+f"(acc[0][nt][3])
                    : "r"(a0.x), "r"(a0.y), "r"(a0.z), "r"(a0.w),
                      "r"(bf[nt][0]), "r"(bf[nt][1]));
                asm volatile(
                    "mma.sync.aligned.m16n8k16.row.col.f32.f16.f16.f32 "
                    "{%0,%1,%2,%3}, {%4,%5,%6,%7}, {%8,%9}, {%0,%1,%2,%3};"
                    : "+f"(acc[1][nt][0]), "+f"(acc[1][nt][1]), "+f"(acc[1][nt][2]), "+f"(acc[1][nt][3])
                    : "r"(a1.x), "r"(a1.y), "r"(a1.z), "r"(a1.w),
                      "r"(bf[nt][0]), "r"(bf[nt][1]));
            }
        }
        // store this w-chunk with ReLU, direct from fragments
        #pragma unroll
        for (int mt = 0; mt < 2; mt++) {
            #pragma unroll
            for (int nt = 0; nt < 8; nt++) {
                const int o = wid * 32 + mt * 16 + g;
                const int w = wc * 64 + nt * 8 + t * 2;
                float* p0 = out + ((size_t)b << 24) + ((size_t)o << 16) + ((size_t)h << 8) + w;
                float2 v0 = make_float2(fmaxf(acc[mt][nt][0], 0.f), fmaxf(acc[mt][nt][1], 0.f));
                float2 v1 = make_float2(fmaxf(acc[mt][nt][2], 0.f), fmaxf(acc[mt][nt][3], 0.f));
                *(float2*)p0 = v0;
                *(float2*)(p0 + (8 << 16)) = v1;
            }
        }
    }
#endif
}

extern "C" void kernel_launch(void* const* d_in, const int* in_sizes, int n_in,
                              void* d_out, int out_size) {
    (void)in_sizes; (void)n_in; (void)out_size;
    const float* x   = (const float*)d_in[0];
    const float* y   = (const float*)d_in[1];
    const float* lnw = (const float*)d_in[2];
    const float* lnb = (const float*)d_in[3];
    const float* cw  = (const float*)d_in[4];
    float* out = (float*)d_out;

    cudaFuncSetAttribute(fused_ln_conv_relu, cudaFuncAttributeMaxDynamicSharedMemorySize, SMEM_TOTAL);

    prep_weights<<<128, 256>>>(cw);
    fused_ln_conv_relu<<<1024, 256, SMEM_TOTAL>>>(x, y, lnw, lnb, out);
}